// round 7
// baseline (speedup 1.0000x reference)
#include <cuda_runtime.h>

// Shapes (fixed)
#define N_TOK 5120     // T*H*W = 5*32*32
#define FDIM  10
#define C_DIM 64
#define HW    1024
#define OUT_ELEMS 51200
#define NPAIR (N_TOK/2)

#define SPLA 128       // n-split for colsum (slice = 40)
#define SPLB 64        // m-split for attn   (slice = 80)
#define MSL  80        // attn m-slice per block
#define NSL  40        // colsum n-slice per block
#define L2E  1.44269504088896f

typedef unsigned long long u64;

// ---------------------------------------------------------------------------
// Scratch (device globals — allocation-free)
// g_qp  [2560][24] : paired q rows (PRE-SCALED by log2e): [2f]=q'[2p][f], [2f+1]=q'[2p+1][f]
// g_qd  [5120][20] : duplicated q, pre-scaled by log2e: (q', q')
// g_kp  [2560][20] : paired k rows (colsum m-pairing)
// g_kvd [5120][48] : [0..19] dup k, [20..39] dup v, [40] Z (atomically built)
// g_stage [5120][12]: output accumulator, contiguous per token
__device__ float g_qp  [NPAIR * 24];
__device__ float g_qd  [N_TOK * 20];
__device__ float g_kp  [NPAIR * 20];
__device__ float g_kvd [N_TOK * 48];
__device__ float g_stage[N_TOK * 12];

// ---------------------------------------------------------------------------
__device__ __forceinline__ u64 fma2(u64 a, u64 b, u64 c) {
    u64 d; asm("fma.rn.f32x2 %0, %1, %2, %3;" : "=l"(d) : "l"(a), "l"(b), "l"(c)); return d;
}
__device__ __forceinline__ u64 add2(u64 a, u64 b) {
    u64 d; asm("add.rn.f32x2 %0, %1, %2;" : "=l"(d) : "l"(a), "l"(b)); return d;
}
__device__ __forceinline__ u64 pk2(float lo, float hi) {
    u64 r; asm("mov.b64 %0, {%1, %2};" : "=l"(r) : "f"(lo), "f"(hi)); return r;
}
__device__ __forceinline__ float2 upk2(u64 v) {
    float2 r; asm("mov.b64 {%0, %1}, %2;" : "=f"(r.x), "=f"(r.y) : "l"(v)); return r;
}
__device__ __forceinline__ float ex2f(float x) {
    float r; asm("ex2.approx.ftz.f32 %0, %1;" : "=f"(r) : "f"(x)); return r;
}
__device__ __forceinline__ float rcpf(float x) {
    float r; asm("rcp.approx.ftz.f32 %0, %1;" : "=f"(r) : "f"(x)); return r;
}

// ---------------------------------------------------------------------------
// Projections + layout packing + scratch init. One thread per token.
__global__ void k_proj(const float* __restrict__ in1, const float* __restrict__ in2,
                       const float* __restrict__ w1, const float* __restrict__ b1,
                       const float* __restrict__ w2, const float* __restrict__ b2,
                       const float* __restrict__ w3, const float* __restrict__ b3) {
    __shared__ float sw1[FDIM * C_DIM], sw2[FDIM * C_DIM], sw3[FDIM * C_DIM];
    int tid = threadIdx.x;
    for (int i = tid; i < FDIM * C_DIM; i += 64) {
        sw1[i] = w1[i]; sw2[i] = w2[i]; sw3[i] = w3[i];
    }
    __syncthreads();

    int n  = blockIdx.x * 64 + tid;
    int t  = n >> 10;
    int hw = n & 1023;
    const float* p1 = in1 + t * (C_DIM * HW) + hw;
    const float* p2 = in2 + t * (C_DIM * HW) + hw;

    // init: this token's stage row + Z slot (replaces old k_init kernel)
    float4 z4 = make_float4(0.f, 0.f, 0.f, 0.f);
    float4* st = (float4*)(g_stage + n * 12);
    st[0] = z4; st[1] = z4; st[2] = z4;

    float qa[FDIM], ka[FDIM], va[FDIM];
#pragma unroll
    for (int f = 0; f < FDIM; f++) { qa[f] = __ldg(b1 + f); ka[f] = __ldg(b2 + f); va[f] = __ldg(b3 + f); }

    for (int c = 0; c < C_DIM; c += 4) {
        float x1[4], x2[4];
#pragma unroll
        for (int u = 0; u < 4; u++) { x1[u] = __ldg(p1 + (c + u) * HW); x2[u] = __ldg(p2 + (c + u) * HW); }
#pragma unroll
        for (int u = 0; u < 4; u++) {
#pragma unroll
            for (int f = 0; f < FDIM; f++) {
                qa[f] = fmaf(sw1[f * C_DIM + c + u], x1[u], qa[f]);
                ka[f] = fmaf(sw2[f * C_DIM + c + u], x2[u], ka[f]);
                va[f] = fmaf(sw3[f * C_DIM + c + u], x1[u], va[f]);
            }
        }
    }

    int p = n >> 1, h = n & 1;
    float* qp = g_qp  + p * 24;
    float* qd = g_qd  + n * 20;
    float* kp = g_kp  + p * 20;
    float* kv = g_kvd + n * 48;
#pragma unroll
    for (int f = 0; f < FDIM; f++) {
        float qs = qa[f] * L2E;              // pre-scale by log2(e)
        qp[2 * f + h] = qs;
        qd[2 * f]     = qs;  qd[2 * f + 1]  = qs;
        kp[2 * f + h] = ka[f];
        kv[2 * f]      = ka[f]; kv[2 * f + 1]  = ka[f];
        kv[20 + 2 * f] = va[f]; kv[21 + 2 * f] = va[f];
    }
    kv[40] = 0.f;                            // Z accumulator init
}

// ---------------------------------------------------------------------------
// Pass A: Z[m] = sum_n exp(q_n . k_m).
// Thread owns 8 m (4 m-pairs, k in regs); block stages an n-slice of dup-q
// rows in smem. grid (5, SPLA), 128 threads.
__global__ void __launch_bounds__(128, 4) k_colsum(void) {
    __shared__ __align__(16) float sq[NSL * 20];
    int tid = threadIdx.x;
    int gt  = blockIdx.x * 128 + tid;            // 0..639
    int n0  = blockIdx.y * NSL;

    for (int i = tid; i < NSL * 5; i += 128) {
        int r = i / 5, c = i - r * 5;
        ((float4*)sq)[r * 5 + c] = __ldg((const float4*)(g_qd + (n0 + r) * 20) + c);
    }
    __syncthreads();

    u64 ka[4][FDIM];
#pragma unroll
    for (int p = 0; p < 4; p++) {
        const ulonglong2* kr = (const ulonglong2*)(g_kp + (4 * gt + p) * 20);
#pragma unroll
        for (int i = 0; i < 5; i++) {
            ulonglong2 v = __ldg(kr + i);
            ka[p][2 * i] = v.x; ka[p][2 * i + 1] = v.y;
        }
    }

    float z[8];
#pragma unroll
    for (int i = 0; i < 8; i++) z[i] = 0.f;

#pragma unroll 2
    for (int nn = 0; nn < NSL; nn++) {
        const ulonglong2* qr = (const ulonglong2*)(sq + nn * 20);
        u64 q[FDIM];
#pragma unroll
        for (int i = 0; i < 5; i++) { ulonglong2 v = qr[i]; q[2 * i] = v.x; q[2 * i + 1] = v.y; }
#pragma unroll
        for (int p = 0; p < 4; p++) {
            u64 s0 = 0ull, s1 = 0ull;
#pragma unroll
            for (int i = 0; i < 5; i++) {
                s0 = fma2(q[2 * i],     ka[p][2 * i],     s0);
                s1 = fma2(q[2 * i + 1], ka[p][2 * i + 1], s1);
            }
            float2 s = upk2(add2(s0, s1));
            z[2 * p]     += ex2f(s.x);
            z[2 * p + 1] += ex2f(s.y);
        }
    }
#pragma unroll
    for (int i = 0; i < 8; i++)
        atomicAdd(&g_kvd[(8 * gt + i) * 48 + 40], z[i]);
}

// ---------------------------------------------------------------------------
// Keeps k_attn at launch index 3 (the ncu capture slot).
__global__ void k_nop(void) {}

// ---------------------------------------------------------------------------
// Pass B: fused relu/sigmoid/softmax. Thread owns 8 n (4 prescaled q-pairs);
// block stages an m-slice of dup k/v + zinv in smem. grid (5, SPLB), 128 thr.
// 256 pairs per warp-iter amortizes the 11 LDS down to 0.16 SM-cyc/pair ->
// fma-pipe becomes the binder (~0.23 SM-cyc/pair).
__global__ void __launch_bounds__(128, 2) k_attn(const float* __restrict__ aw) {
    __shared__ __align__(16) float skv[MSL * 40];
    __shared__ float szinv[MSL];
    int tid = threadIdx.x;
    int gt  = blockIdx.x * 128 + tid;            // 0..639
    int m0  = blockIdx.y * MSL;
    float w0 = __ldg(aw), w1 = __ldg(aw + 1);
    float w0r = w0 * (1.0f / L2E);               // relu on prescaled scores

    for (int i = tid; i < MSL * 10; i += 128) {
        int r = i / 10, c = i - r * 10;
        ((float4*)skv)[r * 10 + c] = __ldg((const float4*)(g_kvd + (m0 + r) * 48) + c);
    }
    if (tid < MSL) szinv[tid] = w0 * rcpf(g_kvd[(m0 + tid) * 48 + 40]);
    __syncthreads();

    // 4 q-pairs (8 n) in registers
    u64 q[4][FDIM];
#pragma unroll
    for (int p = 0; p < 4; p++) {
        const ulonglong2* qr = (const ulonglong2*)(g_qp + (4 * gt + p) * 24);
#pragma unroll
        for (int i = 0; i < 5; i++) {
            ulonglong2 v = __ldg(qr + i);
            q[p][2 * i] = v.x; q[p][2 * i + 1] = v.y;
        }
    }

    u64 acc[4][FDIM];
#pragma unroll
    for (int p = 0; p < 4; p++)
#pragma unroll
        for (int f = 0; f < FDIM; f++) acc[p][f] = 0ull;

#pragma unroll 2
    for (int mm = 0; mm < MSL; mm++) {
        const float* row = skv + mm * 40;
        float zinv = szinv[mm];

        u64 kd[FDIM];
#pragma unroll
        for (int i = 0; i < 5; i++) {
            ulonglong2 kk = ((const ulonglong2*)row)[i];
            kd[2 * i] = kk.x; kd[2 * i + 1] = kk.y;
        }

        // 8 independent 5-deep fma2 chains
        float2 s[4];
#pragma unroll
        for (int p = 0; p < 4; p++) {
            u64 s0 = 0ull, s1 = 0ull;
#pragma unroll
            for (int i = 0; i < 5; i++) {
                s0 = fma2(q[p][2 * i],     kd[2 * i],     s0);
                s1 = fma2(q[p][2 * i + 1], kd[2 * i + 1], s1);
            }
            s[p] = upk2(add2(s0, s1));
        }

        // coef(s') = w0r*max(s',0) + e*(w1*rcp(1+e) + zinv),  e = ex2(s')
        u64 cp[4];
#pragma unroll
        for (int p = 0; p < 4; p++) {
            float e0 = ex2f(s[p].x), e1 = ex2f(s[p].y);
            float c0 = fmaf(e0, fmaf(w1, rcpf(1.f + e0), zinv), w0r * fmaxf(s[p].x, 0.f));
            float c1 = fmaf(e1, fmaf(w1, rcpf(1.f + e1), zinv), w0r * fmaxf(s[p].y, 0.f));
            cp[p] = pk2(c0, c1);
        }

        u64 vd[FDIM];
#pragma unroll
        for (int i = 0; i < 5; i++) {
            ulonglong2 vv = ((const ulonglong2*)(row + 20))[i];
            vd[2 * i] = vv.x; vd[2 * i + 1] = vv.y;
        }
#pragma unroll
        for (int p = 0; p < 4; p++)
#pragma unroll
            for (int f = 0; f < FDIM; f++)
                acc[p][f] = fma2(cp[p], vd[f], acc[p][f]);
    }

    // stage reduction: 8 contiguous token rows -> vector atomics
#pragma unroll
    for (int p = 0; p < 4; p++) {
        float2 u[FDIM];
#pragma unroll
        for (int f = 0; f < FDIM; f++) u[f] = upk2(acc[p][f]);
        float* s0 = g_stage + (gt * 8 + 2 * p)     * 12;
        float* s1 = g_stage + (gt * 8 + 2 * p + 1) * 12;
        atomicAdd((float4*)(s0),     make_float4(u[0].x, u[1].x, u[2].x, u[3].x));
        atomicAdd((float4*)(s0 + 4), make_float4(u[4].x, u[5].x, u[6].x, u[7].x));
        atomicAdd((float2*)(s0 + 8), make_float2(u[8].x, u[9].x));
        atomicAdd((float4*)(s1),     make_float4(u[0].y, u[1].y, u[2].y, u[3].y));
        atomicAdd((float4*)(s1 + 4), make_float4(u[4].y, u[5].y, u[6].y, u[7].y));
        atomicAdd((float2*)(s1 + 8), make_float2(u[8].y, u[9].y));
    }
}

// ---------------------------------------------------------------------------
// Transpose stage -> out[t][f][hw]
__global__ void k_final(float* __restrict__ out) {
    int i = blockIdx.x * 256 + threadIdx.x;     // 0..51199
    int t  = i / (FDIM * HW);
    int r  = i - t * (FDIM * HW);
    int f  = r >> 10;
    int hw = r & 1023;
    out[i] = g_stage[(t * HW + hw) * 12 + f];
}

// ---------------------------------------------------------------------------
extern "C" void kernel_launch(void* const* d_in, const int* in_sizes, int n_in,
                              void* d_out, int out_size) {
    const float* in1 = (const float*)d_in[0];
    const float* in2 = (const float*)d_in[1];
    const float* aw  = (const float*)d_in[2];
    const float* w1  = (const float*)d_in[3];
    const float* b1  = (const float*)d_in[4];
    const float* w2  = (const float*)d_in[5];
    const float* b2  = (const float*)d_in[6];
    const float* w3  = (const float*)d_in[7];
    const float* b3  = (const float*)d_in[8];
    float* out = (float*)d_out;

    k_proj  <<<N_TOK / 64, 64>>>(in1, in2, w1, b1, w2, b2, w3, b3);   // idx 0
    k_colsum<<<dim3(5, SPLA), 128>>>();                               // idx 1
    k_nop   <<<1, 32>>>();                                            // idx 2
    k_attn  <<<dim3(5, SPLB), 128>>>(aw);                             // idx 3  (capture slot)
    k_final <<<OUT_ELEMS / 256, 256>>>(out);                          // idx 4
}

// round 8
// speedup vs baseline: 1.1449x; 1.1449x over previous
#include <cuda_runtime.h>

// Shapes (fixed)
#define N_TOK 5120     // T*H*W = 5*32*32
#define FDIM  10
#define C_DIM 64
#define HW    1024
#define OUT_ELEMS 51200
#define NPAIR (N_TOK/2)

#define SPLA 128       // n-split for colsum (slice = 40)
#define NSL  40        // colsum n-slice per block
#define SPLB 40        // m-split for attn
#define MSL  128       // attn m-slice per block (5120/40)
#define L2E  1.44269504088896f

typedef unsigned long long u64;

// ---------------------------------------------------------------------------
// Scratch (device globals — allocation-free)
// g_q2  [5120][12] : plain q rows, PRE-SCALED by log2e (f-packed dot layout)
// g_qd  [5120][20] : duplicated prescaled q (colsum broadcast rows)
// g_kp  [2560][20] : paired k rows (colsum m-pairing)
// g_kv2 [5120][24] : [0..9] k, [12..21] v, [22] Z (atomic), [10,11,23] pad
// g_stage [5120][12]: output accumulator, contiguous per token
__device__ float g_q2  [N_TOK * 12];
__device__ float g_qd  [N_TOK * 20];
__device__ float g_kp  [NPAIR * 20];
__device__ float g_kv2 [N_TOK * 24];
__device__ float g_stage[N_TOK * 12];

// ---------------------------------------------------------------------------
__device__ __forceinline__ u64 fma2(u64 a, u64 b, u64 c) {
    u64 d; asm("fma.rn.f32x2 %0, %1, %2, %3;" : "=l"(d) : "l"(a), "l"(b), "l"(c)); return d;
}
__device__ __forceinline__ u64 add2(u64 a, u64 b) {
    u64 d; asm("add.rn.f32x2 %0, %1, %2;" : "=l"(d) : "l"(a), "l"(b)); return d;
}
__device__ __forceinline__ u64 pk2(float lo, float hi) {
    u64 r; asm("mov.b64 %0, {%1, %2};" : "=l"(r) : "f"(lo), "f"(hi)); return r;
}
__device__ __forceinline__ float2 upk2(u64 v) {
    float2 r; asm("mov.b64 {%0, %1}, %2;" : "=f"(r.x), "=f"(r.y) : "l"(v)); return r;
}
__device__ __forceinline__ float ex2f(float x) {
    float r; asm("ex2.approx.ftz.f32 %0, %1;" : "=f"(r) : "f"(x)); return r;
}
__device__ __forceinline__ float rcpf(float x) {
    float r; asm("rcp.approx.ftz.f32 %0, %1;" : "=f"(r) : "f"(x)); return r;
}

// ---------------------------------------------------------------------------
// Projections + layout packing + scratch init. One thread per token.
__global__ void k_proj(const float* __restrict__ in1, const float* __restrict__ in2,
                       const float* __restrict__ w1, const float* __restrict__ b1,
                       const float* __restrict__ w2, const float* __restrict__ b2,
                       const float* __restrict__ w3, const float* __restrict__ b3) {
    __shared__ float sw1[FDIM * C_DIM], sw2[FDIM * C_DIM], sw3[FDIM * C_DIM];
    int tid = threadIdx.x;
    for (int i = tid; i < FDIM * C_DIM; i += 64) {
        sw1[i] = w1[i]; sw2[i] = w2[i]; sw3[i] = w3[i];
    }
    __syncthreads();

    int n  = blockIdx.x * 64 + tid;
    int t  = n >> 10;
    int hw = n & 1023;
    const float* p1 = in1 + t * (C_DIM * HW) + hw;
    const float* p2 = in2 + t * (C_DIM * HW) + hw;

    // init this token's stage row (replaces k_init)
    float4 z4 = make_float4(0.f, 0.f, 0.f, 0.f);
    float4* st = (float4*)(g_stage + n * 12);
    st[0] = z4; st[1] = z4; st[2] = z4;

    float qa[FDIM], ka[FDIM], va[FDIM];
#pragma unroll
    for (int f = 0; f < FDIM; f++) { qa[f] = __ldg(b1 + f); ka[f] = __ldg(b2 + f); va[f] = __ldg(b3 + f); }

    for (int c = 0; c < C_DIM; c += 4) {
        float x1[4], x2[4];
#pragma unroll
        for (int u = 0; u < 4; u++) { x1[u] = __ldg(p1 + (c + u) * HW); x2[u] = __ldg(p2 + (c + u) * HW); }
#pragma unroll
        for (int u = 0; u < 4; u++) {
#pragma unroll
            for (int f = 0; f < FDIM; f++) {
                qa[f] = fmaf(sw1[f * C_DIM + c + u], x1[u], qa[f]);
                ka[f] = fmaf(sw2[f * C_DIM + c + u], x2[u], ka[f]);
                va[f] = fmaf(sw3[f * C_DIM + c + u], x1[u], va[f]);
            }
        }
    }

    int p = n >> 1, h = n & 1;
    float* q2 = g_q2  + n * 12;
    float* qd = g_qd  + n * 20;
    float* kp = g_kp  + p * 20;
    float* kv = g_kv2 + n * 24;
#pragma unroll
    for (int f = 0; f < FDIM; f++) {
        float qs = qa[f] * L2E;              // pre-scale by log2(e)
        q2[f]         = qs;
        qd[2 * f]     = qs;  qd[2 * f + 1] = qs;
        kp[2 * f + h] = ka[f];
        kv[f]         = ka[f];
        kv[12 + f]    = va[f];
    }
    q2[10] = 0.f; q2[11] = 0.f;
    kv[10] = 0.f; kv[11] = 0.f;
    kv[22] = 0.f;                            // Z accumulator init
    kv[23] = 0.f;
}

// ---------------------------------------------------------------------------
// Pass A: Z[m] = sum_n exp(q_n . k_m).
// Thread owns 8 m (4 m-pairs, k in regs); block stages an n-slice of dup-q
// rows in smem. grid (5, SPLA), 128 threads.
__global__ void __launch_bounds__(128, 4) k_colsum(void) {
    __shared__ __align__(16) float sq[NSL * 20];
    int tid = threadIdx.x;
    int gt  = blockIdx.x * 128 + tid;            // 0..639
    int n0  = blockIdx.y * NSL;

    for (int i = tid; i < NSL * 5; i += 128) {
        int r = i / 5, c = i - r * 5;
        ((float4*)sq)[r * 5 + c] = __ldg((const float4*)(g_qd + (n0 + r) * 20) + c);
    }
    __syncthreads();

    u64 ka[4][FDIM];
#pragma unroll
    for (int p = 0; p < 4; p++) {
        const ulonglong2* kr = (const ulonglong2*)(g_kp + (4 * gt + p) * 20);
#pragma unroll
        for (int i = 0; i < 5; i++) {
            ulonglong2 v = __ldg(kr + i);
            ka[p][2 * i] = v.x; ka[p][2 * i + 1] = v.y;
        }
    }

    float z[8];
#pragma unroll
    for (int i = 0; i < 8; i++) z[i] = 0.f;

#pragma unroll 2
    for (int nn = 0; nn < NSL; nn++) {
        const ulonglong2* qr = (const ulonglong2*)(sq + nn * 20);
        u64 q[FDIM];
#pragma unroll
        for (int i = 0; i < 5; i++) { ulonglong2 v = qr[i]; q[2 * i] = v.x; q[2 * i + 1] = v.y; }
#pragma unroll
        for (int p = 0; p < 4; p++) {
            u64 s0 = 0ull, s1 = 0ull;
#pragma unroll
            for (int i = 0; i < 5; i++) {
                s0 = fma2(q[2 * i],     ka[p][2 * i],     s0);
                s1 = fma2(q[2 * i + 1], ka[p][2 * i + 1], s1);
            }
            float2 s = upk2(add2(s0, s1));
            z[2 * p]     += ex2f(s.x);
            z[2 * p + 1] += ex2f(s.y);
        }
    }
#pragma unroll
    for (int i = 0; i < 8; i++)
        atomicAdd(&g_kv2[(8 * gt + i) * 24 + 22], z[i]);
}

// ---------------------------------------------------------------------------
// Keeps k_attn at launch index 3 (the ncu capture slot).
__global__ void k_nop(void) {}

// ---------------------------------------------------------------------------
// Pass B: fused relu/sigmoid/softmax. f32x2 packed over the FEATURE dim:
// no k/v duplication (smem row 24 floats), 4 n per thread, ~115 regs ->
// 4 blocks/SM. grid (10, SPLB), 128 threads, single wave of 400 blocks.
__global__ void __launch_bounds__(128, 4) k_attn(const float* __restrict__ aw) {
    __shared__ __align__(16) float skv[MSL * 24];
    int tid = threadIdx.x;
    int gt  = blockIdx.x * 128 + tid;            // 0..1279
    int m0  = blockIdx.y * MSL;
    float w0 = __ldg(aw), w1 = __ldg(aw + 1);
    float w0r = w0 * (1.0f / L2E);               // relu on prescaled scores

    // stage m-slice rows (incl. Z at [22]) : MSL x 6 float4
    for (int i = tid; i < MSL * 6; i += 128) {
        int r = i / 6, c = i - r * 6;
        ((float4*)skv)[r * 6 + c] = __ldg((const float4*)(g_kv2 + (m0 + r) * 24) + c);
    }
    __syncthreads();
    // convert Z -> zinv in place (one row per thread; MSL == blockDim)
    skv[tid * 24 + 22] = w0 * rcpf(skv[tid * 24 + 22]);
    __syncthreads();

    // 4 plain prescaled q rows in registers: qq[p][i] = (q[2i], q[2i+1])
    u64 qq[4][5];
#pragma unroll
    for (int p = 0; p < 4; p++) {
        const float* qr = g_q2 + (4 * gt + p) * 12;
        ulonglong2 a = __ldg((const ulonglong2*)qr);
        ulonglong2 b = __ldg((const ulonglong2*)(qr + 4));
        u64 c = __ldg((const u64*)(qr + 8));
        qq[p][0] = a.x; qq[p][1] = a.y; qq[p][2] = b.x; qq[p][3] = b.y; qq[p][4] = c;
    }

    u64 acc[4][5];
#pragma unroll
    for (int p = 0; p < 4; p++)
#pragma unroll
        for (int i = 0; i < 5; i++) acc[p][i] = 0ull;

    for (int mm = 0; mm < MSL; mm++) {
        const float* row = skv + mm * 24;
        u64 kk[5], vv[5];
        {
            ulonglong2 a = *(const ulonglong2*)row;
            ulonglong2 b = *(const ulonglong2*)(row + 4);
            u64 c = *(const u64*)(row + 8);
            kk[0] = a.x; kk[1] = a.y; kk[2] = b.x; kk[3] = b.y; kk[4] = c;
        }
        float zinv = row[22];

        // 4 independent f-packed dots: (even-f sum, odd-f sum) then horizontal
        float s[4];
#pragma unroll
        for (int p = 0; p < 4; p++) {
            u64 sp = fma2(qq[p][0], kk[0], 0ull);
            u64 sq_ = fma2(qq[p][1], kk[1], 0ull);
            sp = fma2(qq[p][2], kk[2], sp);
            sq_ = fma2(qq[p][3], kk[3], sq_);
            sp = fma2(qq[p][4], kk[4], sp);
            float2 h = upk2(add2(sp, sq_));
            s[p] = h.x + h.y;
        }

        // coef(s') = w0r*max(s',0) + e*(w1*rcp(1+e) + zinv),  e = ex2(s')
        u64 cd[4];
#pragma unroll
        for (int p = 0; p < 4; p++) {
            float e = ex2f(s[p]);
            float c = fmaf(e, fmaf(w1, rcpf(1.f + e), zinv), w0r * fmaxf(s[p], 0.f));
            cd[p] = pk2(c, c);
        }

        {
            ulonglong2 a = *(const ulonglong2*)(row + 12);
            ulonglong2 b = *(const ulonglong2*)(row + 16);
            u64 c = *(const u64*)(row + 20);
            vv[0] = a.x; vv[1] = a.y; vv[2] = b.x; vv[3] = b.y; vv[4] = c;
        }
#pragma unroll
        for (int p = 0; p < 4; p++)
#pragma unroll
            for (int i = 0; i < 5; i++)
                acc[p][i] = fma2(cd[p], vv[i], acc[p][i]);
    }

    // stage reduction: acc[p][i] = (out[2i], out[2i+1]) -> vector atomics
#pragma unroll
    for (int p = 0; p < 4; p++) {
        float2 u[5];
#pragma unroll
        for (int i = 0; i < 5; i++) u[i] = upk2(acc[p][i]);
        float* sr = g_stage + (4 * gt + p) * 12;
        atomicAdd((float4*)(sr),     make_float4(u[0].x, u[0].y, u[1].x, u[1].y));
        atomicAdd((float4*)(sr + 4), make_float4(u[2].x, u[2].y, u[3].x, u[3].y));
        atomicAdd((float2*)(sr + 8), make_float2(u[4].x, u[4].y));
    }
}

// ---------------------------------------------------------------------------
// Transpose stage -> out[t][f][hw]
__global__ void k_final(float* __restrict__ out) {
    int i = blockIdx.x * 256 + threadIdx.x;     // 0..51199
    int t  = i / (FDIM * HW);
    int r  = i - t * (FDIM * HW);
    int f  = r >> 10;
    int hw = r & 1023;
    out[i] = g_stage[(t * HW + hw) * 12 + f];
}

// ---------------------------------------------------------------------------
extern "C" void kernel_launch(void* const* d_in, const int* in_sizes, int n_in,
                              void* d_out, int out_size) {
    const float* in1 = (const float*)d_in[0];
    const float* in2 = (const float*)d_in[1];
    const float* aw  = (const float*)d_in[2];
    const float* w1  = (const float*)d_in[3];
    const float* b1  = (const float*)d_in[4];
    const float* w2  = (const float*)d_in[5];
    const float* b2  = (const float*)d_in[6];
    const float* w3  = (const float*)d_in[7];
    const float* b3  = (const float*)d_in[8];
    float* out = (float*)d_out;

    k_proj  <<<N_TOK / 64, 64>>>(in1, in2, w1, b1, w2, b2, w3, b3);   // idx 0
    k_colsum<<<dim3(5, SPLA), 128>>>();                               // idx 1
    k_nop   <<<1, 32>>>();                                            // idx 2
    k_attn  <<<dim3(10, SPLB), 128>>>(aw);                            // idx 3  (capture slot)
    k_final <<<OUT_ELEMS / 256, 256>>>(out);                          // idx 4
}

// round 10
// speedup vs baseline: 1.1698x; 1.0217x over previous
#include <cuda_runtime.h>

// Shapes (fixed)
#define N_TOK 5120     // T*H*W = 5*32*32
#define FDIM  10
#define C_DIM 64
#define HW    1024
#define OUT_ELEMS 51200
#define NPAIR (N_TOK/2)

#define SPLA 80        // n-split for colsum (slice = 64)
#define NSL  64        // colsum n-slice per block
#define SPLB 40        // m-split for attn
#define MSL  128       // attn m-slice per block (5120/40)
#define L2E  1.44269504088896f

typedef unsigned long long u64;

// ---------------------------------------------------------------------------
// Scratch (device globals — allocation-free)
// g_q2  [5120][12] : plain q rows, PRE-SCALED by log2e (f-packed dot layout)
// g_qd  [5120][20] : duplicated prescaled q (colsum broadcast rows)
// g_kp  [2560][20] : paired k rows (colsum m-pairing)
// g_kv2 [5120][24] : [0..9] k, [12..21] v, [22] Z (atomic), [10,11,23] pad
// g_stage [5120][12]: output accumulator, contiguous per token
__device__ float g_q2  [N_TOK * 12];
__device__ float g_qd  [N_TOK * 20];
__device__ float g_kp  [NPAIR * 20];
__device__ float g_kv2 [N_TOK * 24];
__device__ float g_stage[N_TOK * 12];

// ---------------------------------------------------------------------------
__device__ __forceinline__ u64 fma2(u64 a, u64 b, u64 c) {
    u64 d; asm("fma.rn.f32x2 %0, %1, %2, %3;" : "=l"(d) : "l"(a), "l"(b), "l"(c)); return d;
}
__device__ __forceinline__ u64 add2(u64 a, u64 b) {
    u64 d; asm("add.rn.f32x2 %0, %1, %2;" : "=l"(d) : "l"(a), "l"(b)); return d;
}
__device__ __forceinline__ u64 pk2(float lo, float hi) {
    u64 r; asm("mov.b64 %0, {%1, %2};" : "=l"(r) : "f"(lo), "f"(hi)); return r;
}
__device__ __forceinline__ float2 upk2(u64 v) {
    float2 r; asm("mov.b64 {%0, %1}, %2;" : "=f"(r.x), "=f"(r.y) : "l"(v)); return r;
}
__device__ __forceinline__ float ex2f(float x) {
    float r; asm("ex2.approx.ftz.f32 %0, %1;" : "=f"(r) : "f"(x)); return r;
}
__device__ __forceinline__ float rcpf(float x) {
    float r; asm("rcp.approx.ftz.f32 %0, %1;" : "=f"(r) : "f"(x)); return r;
}

// ---------------------------------------------------------------------------
// Projections + layout packing + scratch init. One thread per token.
__global__ void k_proj(const float* __restrict__ in1, const float* __restrict__ in2,
                       const float* __restrict__ w1, const float* __restrict__ b1,
                       const float* __restrict__ w2, const float* __restrict__ b2,
                       const float* __restrict__ w3, const float* __restrict__ b3) {
    __shared__ float sw1[FDIM * C_DIM], sw2[FDIM * C_DIM], sw3[FDIM * C_DIM];
    int tid = threadIdx.x;
    for (int i = tid; i < FDIM * C_DIM; i += 64) {
        sw1[i] = w1[i]; sw2[i] = w2[i]; sw3[i] = w3[i];
    }
    __syncthreads();

    int n  = blockIdx.x * 64 + tid;
    int t  = n >> 10;
    int hw = n & 1023;
    const float* p1 = in1 + t * (C_DIM * HW) + hw;
    const float* p2 = in2 + t * (C_DIM * HW) + hw;

    // init this token's stage row (replaces k_init)
    float4 z4 = make_float4(0.f, 0.f, 0.f, 0.f);
    float4* st = (float4*)(g_stage + n * 12);
    st[0] = z4; st[1] = z4; st[2] = z4;

    float qa[FDIM], ka[FDIM], va[FDIM];
#pragma unroll
    for (int f = 0; f < FDIM; f++) { qa[f] = __ldg(b1 + f); ka[f] = __ldg(b2 + f); va[f] = __ldg(b3 + f); }

    for (int c = 0; c < C_DIM; c += 4) {
        float x1[4], x2[4];
#pragma unroll
        for (int u = 0; u < 4; u++) { x1[u] = __ldg(p1 + (c + u) * HW); x2[u] = __ldg(p2 + (c + u) * HW); }
#pragma unroll
        for (int u = 0; u < 4; u++) {
#pragma unroll
            for (int f = 0; f < FDIM; f++) {
                qa[f] = fmaf(sw1[f * C_DIM + c + u], x1[u], qa[f]);
                ka[f] = fmaf(sw2[f * C_DIM + c + u], x2[u], ka[f]);
                va[f] = fmaf(sw3[f * C_DIM + c + u], x1[u], va[f]);
            }
        }
    }

    int p = n >> 1, h = n & 1;
    float* q2 = g_q2  + n * 12;
    float* qd = g_qd  + n * 20;
    float* kp = g_kp  + p * 20;
    float* kv = g_kv2 + n * 24;
#pragma unroll
    for (int f = 0; f < FDIM; f++) {
        float qs = qa[f] * L2E;              // pre-scale by log2(e)
        q2[f]         = qs;
        qd[2 * f]     = qs;  qd[2 * f + 1] = qs;
        kp[2 * f + h] = ka[f];
        kv[f]         = ka[f];
        kv[12 + f]    = va[f];
    }
    q2[10] = 0.f; q2[11] = 0.f;
    kv[10] = 0.f; kv[11] = 0.f;
    kv[22] = 0.f;                            // Z accumulator init
    kv[23] = 0.f;
}

// ---------------------------------------------------------------------------
// Pass A: Z[m] = sum_n exp(q_n . k_m).
// Thread owns 8 m (4 m-pairs, k in regs); block stages an n-slice of dup-q
// rows in smem. grid (5, SPLA) = 400 blocks (no second-wave tail), 128 thr.
__global__ void __launch_bounds__(128, 4) k_colsum(void) {
    __shared__ __align__(16) float sq[NSL * 20];
    int tid = threadIdx.x;
    int gt  = blockIdx.x * 128 + tid;            // 0..639
    int n0  = blockIdx.y * NSL;

    for (int i = tid; i < NSL * 5; i += 128) {
        int r = i / 5, c = i - r * 5;
        ((float4*)sq)[r * 5 + c] = __ldg((const float4*)(g_qd + (n0 + r) * 20) + c);
    }
    __syncthreads();

    u64 ka[4][FDIM];
#pragma unroll
    for (int p = 0; p < 4; p++) {
        const ulonglong2* kr = (const ulonglong2*)(g_kp + (4 * gt + p) * 20);
#pragma unroll
        for (int i = 0; i < 5; i++) {
            ulonglong2 v = __ldg(kr + i);
            ka[p][2 * i] = v.x; ka[p][2 * i + 1] = v.y;
        }
    }

    float z[8];
#pragma unroll
    for (int i = 0; i < 8; i++) z[i] = 0.f;

#pragma unroll 2
    for (int nn = 0; nn < NSL; nn++) {
        const ulonglong2* qr = (const ulonglong2*)(sq + nn * 20);
        u64 q[FDIM];
#pragma unroll
        for (int i = 0; i < 5; i++) { ulonglong2 v = qr[i]; q[2 * i] = v.x; q[2 * i + 1] = v.y; }
#pragma unroll
        for (int p = 0; p < 4; p++) {
            u64 s0 = 0ull, s1 = 0ull;
#pragma unroll
            for (int i = 0; i < 5; i++) {
                s0 = fma2(q[2 * i],     ka[p][2 * i],     s0);
                s1 = fma2(q[2 * i + 1], ka[p][2 * i + 1], s1);
            }
            float2 s = upk2(add2(s0, s1));
            z[2 * p]     += ex2f(s.x);
            z[2 * p + 1] += ex2f(s.y);
        }
    }
#pragma unroll
    for (int i = 0; i < 8; i++)
        atomicAdd(&g_kv2[(8 * gt + i) * 24 + 22], z[i]);
}

// ---------------------------------------------------------------------------
// Keeps k_attn at launch index 3 (the ncu capture slot).
__global__ void k_nop(void) {}

// ---------------------------------------------------------------------------
// Pass B: fused relu/sigmoid/softmax. f32x2 packed over the FEATURE dim,
// 2 n per thread (~70 regs -> 3 blocks/SM co-residency; 400-block grid gives
// ~5.4 warps/SMSP for latency hiding). grid (10, SPLB), 256 threads.
__global__ void __launch_bounds__(256, 3) k_attn(const float* __restrict__ aw) {
    __shared__ __align__(16) float skv[MSL * 24];
    int tid = threadIdx.x;
    int gt  = blockIdx.x * 256 + tid;            // 0..2559
    int m0  = blockIdx.y * MSL;
    float w0 = __ldg(aw), w1 = __ldg(aw + 1);
    float w0r = w0 * (1.0f / L2E);               // relu on prescaled scores

    // stage m-slice rows (incl. Z at [22]) : MSL x 6 float4
    for (int i = tid; i < MSL * 6; i += 256) {
        int r = i / 6, c = i - r * 6;
        ((float4*)skv)[r * 6 + c] = __ldg((const float4*)(g_kv2 + (m0 + r) * 24) + c);
    }
    __syncthreads();
    // convert Z -> zinv in place (MSL=128 rows, first 128 threads)
    if (tid < MSL) skv[tid * 24 + 22] = w0 * rcpf(skv[tid * 24 + 22]);
    __syncthreads();

    // 2 plain prescaled q rows in registers: qq[p][i] = (q[2i], q[2i+1])
    u64 qq[2][5];
#pragma unroll
    for (int p = 0; p < 2; p++) {
        const float* qr = g_q2 + (2 * gt + p) * 12;
        ulonglong2 a = __ldg((const ulonglong2*)qr);
        ulonglong2 b = __ldg((const ulonglong2*)(qr + 4));
        u64 c = __ldg((const u64*)(qr + 8));
        qq[p][0] = a.x; qq[p][1] = a.y; qq[p][2] = b.x; qq[p][3] = b.y; qq[p][4] = c;
    }

    u64 acc[2][5];
#pragma unroll
    for (int p = 0; p < 2; p++)
#pragma unroll
        for (int i = 0; i < 5; i++) acc[p][i] = 0ull;

#pragma unroll 2
    for (int mm = 0; mm < MSL; mm++) {
        const float* row = skv + mm * 24;
        u64 kk[5], vv[5];
        {
            ulonglong2 a = *(const ulonglong2*)row;
            ulonglong2 b = *(const ulonglong2*)(row + 4);
            u64 c = *(const u64*)(row + 8);
            kk[0] = a.x; kk[1] = a.y; kk[2] = b.x; kk[3] = b.y; kk[4] = c;
        }
        float zinv = row[22];

        // 2 independent f-packed dots: (even-f sum, odd-f sum) then horizontal
        float s[2];
#pragma unroll
        for (int p = 0; p < 2; p++) {
            u64 se = fma2(qq[p][0], kk[0], 0ull);
            u64 so = fma2(qq[p][1], kk[1], 0ull);
            se = fma2(qq[p][2], kk[2], se);
            so = fma2(qq[p][3], kk[3], so);
            se = fma2(qq[p][4], kk[4], se);
            float2 h = upk2(add2(se, so));
            s[p] = h.x + h.y;
        }

        // coef(s') = w0r*max(s',0) + e*(w1*rcp(1+e) + zinv),  e = ex2(s')
        u64 cd[2];
#pragma unroll
        for (int p = 0; p < 2; p++) {
            float e = ex2f(s[p]);
            float c = fmaf(e, fmaf(w1, rcpf(1.f + e), zinv), w0r * fmaxf(s[p], 0.f));
            cd[p] = pk2(c, c);
        }

        {
            ulonglong2 a = *(const ulonglong2*)(row + 12);
            ulonglong2 b = *(const ulonglong2*)(row + 16);
            u64 c = *(const u64*)(row + 20);
            vv[0] = a.x; vv[1] = a.y; vv[2] = b.x; vv[3] = b.y; vv[4] = c;
        }
#pragma unroll
        for (int p = 0; p < 2; p++)
#pragma unroll
            for (int i = 0; i < 5; i++)
                acc[p][i] = fma2(cd[p], vv[i], acc[p][i]);
    }

    // stage reduction: acc[p][i] = (out[2i], out[2i+1]) -> vector atomics
#pragma unroll
    for (int p = 0; p < 2; p++) {
        float2 u[5];
#pragma unroll
        for (int i = 0; i < 5; i++) u[i] = upk2(acc[p][i]);
        float* sr = g_stage + (2 * gt + p) * 12;
        atomicAdd((float4*)(sr),     make_float4(u[0].x, u[0].y, u[1].x, u[1].y));
        atomicAdd((float4*)(sr + 4), make_float4(u[2].x, u[2].y, u[3].x, u[3].y));
        atomicAdd((float2*)(sr + 8), make_float2(u[4].x, u[4].y));
    }
}

// ---------------------------------------------------------------------------
// Transpose stage -> out[t][f][hw]
__global__ void k_final(float* __restrict__ out) {
    int i = blockIdx.x * 256 + threadIdx.x;     // 0..51199
    int t  = i / (FDIM * HW);
    int r  = i - t * (FDIM * HW);
    int f  = r >> 10;
    int hw = r & 1023;
    out[i] = g_stage[(t * HW + hw) * 12 + f];
}

// ---------------------------------------------------------------------------
extern "C" void kernel_launch(void* const* d_in, const int* in_sizes, int n_in,
                              void* d_out, int out_size) {
    const float* in1 = (const float*)d_in[0];
    const float* in2 = (const float*)d_in[1];
    const float* aw  = (const float*)d_in[2];
    const float* w1  = (const float*)d_in[3];
    const float* b1  = (const float*)d_in[4];
    const float* w2  = (const float*)d_in[5];
    const float* b2  = (const float*)d_in[6];
    const float* w3  = (const float*)d_in[7];
    const float* b3  = (const float*)d_in[8];
    float* out = (float*)d_out;

    k_proj  <<<N_TOK / 64, 64>>>(in1, in2, w1, b1, w2, b2, w3, b3);   // idx 0
    k_colsum<<<dim3(5, SPLA), 128>>>();                               // idx 1
    k_nop   <<<1, 32>>>();                                            // idx 2
    k_attn  <<<dim3(10, SPLB), 256>>>(aw);                            // idx 3  (capture slot)
    k_final <<<OUT_ELEMS / 256, 256>>>(out);                          // idx 4
}

// round 12
// speedup vs baseline: 1.2743x; 1.0893x over previous
#include <cuda_runtime.h>

// Shapes (fixed)
#define N_TOK 5120     // T*H*W = 5*32*32
#define FDIM  10
#define C_DIM 64
#define HW    1024
#define OUT_ELEMS 51200
#define NPAIR (N_TOK/2)

#define SPLA 80        // n-split for colsum (slice = 64)
#define NSL  64        // colsum n-slice per block
#define SPLB 40        // m-split for attn
#define MSL  128       // attn m-slice per block (5120/40)
#define L2E  1.44269504088896f

typedef unsigned long long u64;

// ---------------------------------------------------------------------------
// Scratch (device globals — allocation-free)
// g_q2  [5120][12] : plain q rows, PRE-SCALED by log2e (f-packed dot layout)
// g_qd  [5120][20] : duplicated prescaled q (colsum broadcast rows)
// g_kp  [2560][20] : paired k rows (colsum m-pairing)
// g_kv2 [5120][24] : [0..9] k, [12..21] v, [22] Z->zinv, [10,11,23] pad
// g_stage [5120][12]: output accumulator, contiguous per token
__device__ float g_q2  [N_TOK * 12];
__device__ float g_qd  [N_TOK * 20];
__device__ float g_kp  [NPAIR * 20];
__device__ float g_kv2 [N_TOK * 24];
__device__ float g_stage[N_TOK * 12];

// ---------------------------------------------------------------------------
__device__ __forceinline__ u64 fma2(u64 a, u64 b, u64 c) {
    u64 d; asm("fma.rn.f32x2 %0, %1, %2, %3;" : "=l"(d) : "l"(a), "l"(b), "l"(c)); return d;
}
__device__ __forceinline__ u64 add2(u64 a, u64 b) {
    u64 d; asm("add.rn.f32x2 %0, %1, %2;" : "=l"(d) : "l"(a), "l"(b)); return d;
}
__device__ __forceinline__ u64 pk2(float lo, float hi) {
    u64 r; asm("mov.b64 %0, {%1, %2};" : "=l"(r) : "f"(lo), "f"(hi)); return r;
}
__device__ __forceinline__ float2 upk2(u64 v) {
    float2 r; asm("mov.b64 {%0, %1}, %2;" : "=f"(r.x), "=f"(r.y) : "l"(v)); return r;
}
__device__ __forceinline__ float ex2f(float x) {
    float r; asm("ex2.approx.ftz.f32 %0, %1;" : "=f"(r) : "f"(x)); return r;
}
__device__ __forceinline__ float rcpf(float x) {
    float r; asm("rcp.approx.ftz.f32 %0, %1;" : "=f"(r) : "f"(x)); return r;
}

// ---------------------------------------------------------------------------
// Projections: block = 32 tokens x 4 channel-groups (128 threads, 160 blocks).
// Each thread reduces 16 channels; partials combined via padded smem; packing
// phase is (token, f)-parallel. Also inits stage rows + pads + Z.
__global__ void __launch_bounds__(128) k_proj(
        const float* __restrict__ in1, const float* __restrict__ in2,
        const float* __restrict__ w1, const float* __restrict__ b1,
        const float* __restrict__ w2, const float* __restrict__ b2,
        const float* __restrict__ w3, const float* __restrict__ b3) {
    __shared__ float sw1[FDIM * C_DIM], sw2[FDIM * C_DIM], sw3[FDIM * C_DIM];
    __shared__ float part[32 * 32 * 5];        // [idx(30 used)][tok][cg pad 5]
    int tid = threadIdx.x;
    for (int i = tid; i < FDIM * C_DIM; i += 128) {
        sw1[i] = w1[i]; sw2[i] = w2[i]; sw3[i] = w3[i];
    }
    __syncthreads();

    int tok = tid & 31, cg = tid >> 5;         // cg in 0..3
    int n  = blockIdx.x * 32 + tok;
    int t  = n >> 10;
    int hw = n & 1023;
    int c0 = cg * 16;
    const float* p1 = in1 + t * (C_DIM * HW) + hw + c0 * HW;
    const float* p2 = in2 + t * (C_DIM * HW) + hw + c0 * HW;

    float qa[FDIM], ka[FDIM], va[FDIM];
    if (cg == 0) {
#pragma unroll
        for (int f = 0; f < FDIM; f++) { qa[f] = __ldg(b1 + f); ka[f] = __ldg(b2 + f); va[f] = __ldg(b3 + f); }
    } else {
#pragma unroll
        for (int f = 0; f < FDIM; f++) { qa[f] = 0.f; ka[f] = 0.f; va[f] = 0.f; }
    }

    for (int c = 0; c < 16; c += 4) {
        float x1[4], x2[4];
#pragma unroll
        for (int u = 0; u < 4; u++) { x1[u] = __ldg(p1 + (c + u) * HW); x2[u] = __ldg(p2 + (c + u) * HW); }
#pragma unroll
        for (int u = 0; u < 4; u++) {
#pragma unroll
            for (int f = 0; f < FDIM; f++) {
                qa[f] = fmaf(sw1[f * C_DIM + c0 + c + u], x1[u], qa[f]);
                ka[f] = fmaf(sw2[f * C_DIM + c0 + c + u], x2[u], ka[f]);
                va[f] = fmaf(sw3[f * C_DIM + c0 + c + u], x1[u], va[f]);
            }
        }
    }

    // partials: idx 0..9 q, 10..19 k, 20..29 v ; addr = (idx*32 + tok)*5 + cg
#pragma unroll
    for (int f = 0; f < FDIM; f++) {
        part[(f * 32 + tok) * 5 + cg]        = qa[f];
        part[((10 + f) * 32 + tok) * 5 + cg] = ka[f];
        part[((20 + f) * 32 + tok) * 5 + cg] = va[f];
    }
    __syncthreads();

    // reduce + pack: thread (chunk=cg, tok) handles idx in [8*chunk, 8*chunk+8)
    int n2 = blockIdx.x * 32 + tok;
    int pr = n2 >> 1, hb = n2 & 1;
#pragma unroll
    for (int j = 0; j < 8; j++) {
        int idx = cg * 8 + j;
        if (idx >= 30) break;
        const float* pp = part + idx * 160 + tok * 5;
        float s = (pp[0] + pp[1]) + (pp[2] + pp[3]);
        if (idx < 10) {
            float qs = s * L2E;
            g_q2[n2 * 12 + idx] = qs;
            g_qd[n2 * 20 + 2 * idx]     = qs;
            g_qd[n2 * 20 + 2 * idx + 1] = qs;
        } else if (idx < 20) {
            int f = idx - 10;
            g_kp[pr * 20 + 2 * f + hb] = s;
            g_kv2[n2 * 24 + f] = s;
        } else {
            g_kv2[n2 * 24 + 12 + (idx - 20)] = s;
        }
    }
    // pads / Z / stage init (uniform-per-warp branches)
    if (cg < 3) {
        ((float4*)(g_stage + n2 * 12))[cg] = make_float4(0.f, 0.f, 0.f, 0.f);
    } else {
        g_q2[n2 * 12 + 10] = 0.f; g_q2[n2 * 12 + 11] = 0.f;
        g_kv2[n2 * 24 + 10] = 0.f; g_kv2[n2 * 24 + 11] = 0.f;
        g_kv2[n2 * 24 + 22] = 0.f; g_kv2[n2 * 24 + 23] = 0.f;
    }
}

// ---------------------------------------------------------------------------
// Pass A: Z[m] = sum_n exp(q_n . k_m).
// Thread owns 8 m (4 m-pairs, k in regs); block stages an n-slice of dup-q
// rows in smem. grid (5, SPLA) = 400 blocks (single wave), 128 thr.
__global__ void __launch_bounds__(128, 4) k_colsum(void) {
    __shared__ __align__(16) float sq[NSL * 20];
    int tid = threadIdx.x;
    int gt  = blockIdx.x * 128 + tid;            // 0..639
    int n0  = blockIdx.y * NSL;

    for (int i = tid; i < NSL * 5; i += 128) {
        int r = i / 5, c = i - r * 5;
        ((float4*)sq)[r * 5 + c] = __ldg((const float4*)(g_qd + (n0 + r) * 20) + c);
    }
    __syncthreads();

    u64 ka[4][FDIM];
#pragma unroll
    for (int p = 0; p < 4; p++) {
        const ulonglong2* kr = (const ulonglong2*)(g_kp + (4 * gt + p) * 20);
#pragma unroll
        for (int i = 0; i < 5; i++) {
            ulonglong2 v = __ldg(kr + i);
            ka[p][2 * i] = v.x; ka[p][2 * i + 1] = v.y;
        }
    }

    float z[8];
#pragma unroll
    for (int i = 0; i < 8; i++) z[i] = 0.f;

#pragma unroll 2
    for (int nn = 0; nn < NSL; nn++) {
        const ulonglong2* qr = (const ulonglong2*)(sq + nn * 20);
        u64 q[FDIM];
#pragma unroll
        for (int i = 0; i < 5; i++) { ulonglong2 v = qr[i]; q[2 * i] = v.x; q[2 * i + 1] = v.y; }
#pragma unroll
        for (int p = 0; p < 4; p++) {
            u64 s0 = 0ull, s1 = 0ull;
#pragma unroll
            for (int i = 0; i < 5; i++) {
                s0 = fma2(q[2 * i],     ka[p][2 * i],     s0);
                s1 = fma2(q[2 * i + 1], ka[p][2 * i + 1], s1);
            }
            float2 s = upk2(add2(s0, s1));
            z[2 * p]     += ex2f(s.x);
            z[2 * p + 1] += ex2f(s.y);
        }
    }
#pragma unroll
    for (int i = 0; i < 8; i++)
        atomicAdd(&g_kv2[(8 * gt + i) * 24 + 22], z[i]);
}

// ---------------------------------------------------------------------------
// Z -> zinv = w0 / Z, in place (replaces the old capture-slot nop usefully).
__global__ void k_zinv2(const float* __restrict__ aw) {
    int m = blockIdx.x * 256 + threadIdx.x;
    if (m < N_TOK) {
        float w0 = __ldg(aw);
        g_kv2[m * 24 + 22] = w0 * rcpf(g_kv2[m * 24 + 22]);
    }
}

// ---------------------------------------------------------------------------
// Pass B: fused relu/sigmoid/softmax. f32x2 packed over the FEATURE dim,
// 2 n per thread. grid (10, SPLB) = 400 blocks, 256 threads, 3 blocks/SM.
__global__ void __launch_bounds__(256, 3) k_attn(const float* __restrict__ aw) {
    __shared__ __align__(16) float skv[MSL * 24];
    int tid = threadIdx.x;
    int gt  = blockIdx.x * 256 + tid;            // 0..2559
    int m0  = blockIdx.y * MSL;
    float w0 = __ldg(aw), w1 = __ldg(aw + 1);
    float w0r = w0 * (1.0f / L2E);               // relu on prescaled scores

    // stage m-slice rows (zinv already in [22]) : MSL x 6 float4
    for (int i = tid; i < MSL * 6; i += 256) {
        int r = i / 6, c = i - r * 6;
        ((float4*)skv)[r * 6 + c] = __ldg((const float4*)(g_kv2 + (m0 + r) * 24) + c);
    }
    __syncthreads();

    // 2 plain prescaled q rows in registers: qq[p][i] = (q[2i], q[2i+1])
    u64 qq[2][5];
#pragma unroll
    for (int p = 0; p < 2; p++) {
        const float* qr = g_q2 + (2 * gt + p) * 12;
        ulonglong2 a = __ldg((const ulonglong2*)qr);
        ulonglong2 b = __ldg((const ulonglong2*)(qr + 4));
        u64 c = __ldg((const u64*)(qr + 8));
        qq[p][0] = a.x; qq[p][1] = a.y; qq[p][2] = b.x; qq[p][3] = b.y; qq[p][4] = c;
    }

    u64 acc[2][5];
#pragma unroll
    for (int p = 0; p < 2; p++)
#pragma unroll
        for (int i = 0; i < 5; i++) acc[p][i] = 0ull;

#pragma unroll 2
    for (int mm = 0; mm < MSL; mm++) {
        const float* row = skv + mm * 24;
        u64 kk[5], vv[5];
        {
            ulonglong2 a = *(const ulonglong2*)row;
            ulonglong2 b = *(const ulonglong2*)(row + 4);
            u64 c = *(const u64*)(row + 8);
            kk[0] = a.x; kk[1] = a.y; kk[2] = b.x; kk[3] = b.y; kk[4] = c;
        }
        float zinv = row[22];

        // 2 independent f-packed dots: (even-f sum, odd-f sum) then horizontal
        float s[2];
#pragma unroll
        for (int p = 0; p < 2; p++) {
            u64 se = fma2(qq[p][0], kk[0], 0ull);
            u64 so = fma2(qq[p][1], kk[1], 0ull);
            se = fma2(qq[p][2], kk[2], se);
            so = fma2(qq[p][3], kk[3], so);
            se = fma2(qq[p][4], kk[4], se);
            float2 h = upk2(add2(se, so));
            s[p] = h.x + h.y;
        }

        // coef(s') = w0r*max(s',0) + e*(w1*rcp(1+e) + zinv),  e = ex2(s')
        u64 cd[2];
#pragma unroll
        for (int p = 0; p < 2; p++) {
            float e = ex2f(s[p]);
            float c = fmaf(e, fmaf(w1, rcpf(1.f + e), zinv), w0r * fmaxf(s[p], 0.f));
            cd[p] = pk2(c, c);
        }

        {
            ulonglong2 a = *(const ulonglong2*)(row + 12);
            ulonglong2 b = *(const ulonglong2*)(row + 16);
            u64 c = *(const u64*)(row + 20);
            vv[0] = a.x; vv[1] = a.y; vv[2] = b.x; vv[3] = b.y; vv[4] = c;
        }
#pragma unroll
        for (int p = 0; p < 2; p++)
#pragma unroll
            for (int i = 0; i < 5; i++)
                acc[p][i] = fma2(cd[p], vv[i], acc[p][i]);
    }

    // stage reduction: acc[p][i] = (out[2i], out[2i+1]) -> vector atomics
#pragma unroll
    for (int p = 0; p < 2; p++) {
        float2 u[5];
#pragma unroll
        for (int i = 0; i < 5; i++) u[i] = upk2(acc[p][i]);
        float* sr = g_stage + (2 * gt + p) * 12;
        atomicAdd((float4*)(sr),     make_float4(u[0].x, u[0].y, u[1].x, u[1].y));
        atomicAdd((float4*)(sr + 4), make_float4(u[2].x, u[2].y, u[3].x, u[3].y));
        atomicAdd((float2*)(sr + 8), make_float2(u[4].x, u[4].y));
    }
}

// ---------------------------------------------------------------------------
// Transpose stage -> out[t][f][hw]
__global__ void k_final(float* __restrict__ out) {
    int i = blockIdx.x * 256 + threadIdx.x;     // 0..51199
    int t  = i / (FDIM * HW);
    int r  = i - t * (FDIM * HW);
    int f  = r >> 10;
    int hw = r & 1023;
    out[i] = g_stage[(t * HW + hw) * 12 + f];
}

// ---------------------------------------------------------------------------
extern "C" void kernel_launch(void* const* d_in, const int* in_sizes, int n_in,
                              void* d_out, int out_size) {
    const float* in1 = (const float*)d_in[0];
    const float* in2 = (const float*)d_in[1];
    const float* aw  = (const float*)d_in[2];
    const float* w1  = (const float*)d_in[3];
    const float* b1  = (const float*)d_in[4];
    const float* w2  = (const float*)d_in[5];
    const float* b2  = (const float*)d_in[6];
    const float* w3  = (const float*)d_in[7];
    const float* b3  = (const float*)d_in[8];
    float* out = (float*)d_out;

    k_proj  <<<N_TOK / 32, 128>>>(in1, in2, w1, b1, w2, b2, w3, b3);  // idx 0
    k_colsum<<<dim3(5, SPLA), 128>>>();                               // idx 1
    k_zinv2 <<<20, 256>>>(aw);                                        // idx 2
    k_attn  <<<dim3(10, SPLB), 256>>>(aw);                            // idx 3  (capture slot)
    k_final <<<OUT_ELEMS / 256, 256>>>(out);                          // idx 4
}